// round 4
// baseline (speedup 1.0000x reference)
#include <cuda_runtime.h>
#include <math.h>

// Problem dims
#define B_   32
#define T_   64
#define S_   64
#define V_   32000
#define E_   512
#define H_   1024
#define G4_  4096      // 4*H
#define TS_  63        // T-1 decode steps
#define M2_  2016      // TS_*B_ total (t,b) rows
#define MP_  2048      // padded row count for GEMM tiles

// Scratch (device globals: no allocation allowed)
__device__ float g_xw[MP_ * G4_];      // x@W_ih^T + bias, per (t,b) row   (32 MB)
__device__ float g_gates[B_ * G4_];    // current-step gates
__device__ float g_h[B_ * H_];
__device__ float g_c[B_ * H_];
__device__ float g_hc[B_ * 2 * H_];    // [h, context] concat per batch
__device__ float g_dec[MP_ * H_];      // tanh(dec) rows, padded (zeros beyond M2_)

// ---------------------------------------------------------------------------
// init h, c from inputs
__global__ void k_init(const float* __restrict__ h0, const float* __restrict__ c0) {
    int i = blockIdx.x * blockDim.x + threadIdx.x;
    if (i < B_ * H_) { g_h[i] = h0[i]; g_c[i] = c0[i]; }
}

// ---------------------------------------------------------------------------
// Kernel 1: g_xw[m, n] = sum_k emb[tgt(m), k] * W_ih[n, k] + (b_ih[n]+b_hh[n])
// m = t*32 + b;  64x64 tile, BK=16, 256 threads, 4x4 micro-tile.
__global__ __launch_bounds__(256) void k_embed_xw(
    const int* __restrict__ tgt, const float* __restrict__ emb,
    const float* __restrict__ W_ih, const float* __restrict__ b_ih,
    const float* __restrict__ b_hh)
{
    __shared__ float As[16][68];
    __shared__ float Bs[16][68];
    const int tid = threadIdx.x;
    const int tx = tid & 15, ty = tid >> 4;
    const int n0 = blockIdx.x * 64;
    const int m0 = blockIdx.y * 64;

    // gathered embedding row for the A float4 this thread loads (64 rows x 4 f4)
    const int mA = tid >> 2;            // 0..63
    const int kqA = (tid & 3) * 4;      // 0,4,8,12
    int gmA = m0 + mA;
    int tA = gmA >> 5, bA = gmA & 31;
    const int rowA = (tA < TS_) ? tgt[bA * T_ + tA] : 0;

    float acc[4][4] = {};
    for (int k0 = 0; k0 < E_; k0 += 16) {
        {
            float4 v = *reinterpret_cast<const float4*>(&emb[(size_t)rowA * E_ + k0 + kqA]);
            As[kqA + 0][mA] = v.x; As[kqA + 1][mA] = v.y;
            As[kqA + 2][mA] = v.z; As[kqA + 3][mA] = v.w;
            float4 w = *reinterpret_cast<const float4*>(&W_ih[(size_t)(n0 + mA) * E_ + k0 + kqA]);
            Bs[kqA + 0][mA] = w.x; Bs[kqA + 1][mA] = w.y;
            Bs[kqA + 2][mA] = w.z; Bs[kqA + 3][mA] = w.w;
        }
        __syncthreads();
#pragma unroll
        for (int k = 0; k < 16; k++) {
            float a[4], bb[4];
#pragma unroll
            for (int i = 0; i < 4; i++) a[i]  = As[k][ty * 4 + i];
#pragma unroll
            for (int j = 0; j < 4; j++) bb[j] = Bs[k][tx * 4 + j];
#pragma unroll
            for (int i = 0; i < 4; i++)
#pragma unroll
                for (int j = 0; j < 4; j++) acc[i][j] += a[i] * bb[j];
        }
        __syncthreads();
    }
#pragma unroll
    for (int i = 0; i < 4; i++) {
        int gm = m0 + ty * 4 + i;
#pragma unroll
        for (int j = 0; j < 4; j++) {
            int gn = n0 + tx * 4 + j;
            g_xw[(size_t)gm * G4_ + gn] = acc[i][j] + b_ih[gn] + b_hh[gn];
        }
    }
}

// ---------------------------------------------------------------------------
// Kernel 2 (per step): g_gates[m, n] = sum_k g_h[m,k]*W_hh[n,k] + g_xw[t*32+m, n]
// M=32, N=4096, K=1024.  32x32 tile, BK=32, 256 threads, 2x2 micro-tile. grid=128.
// float4 global loads: 32x32 tile = 256 float4, 1 per thread.
__global__ __launch_bounds__(256) void k_gemm_hh(const float* __restrict__ W_hh, int t) {
    __shared__ float As[32][33];
    __shared__ float Bs[32][33];
    const int tid = threadIdx.x;
    const int tx = tid & 15, ty = tid >> 4;
    const int n0 = blockIdx.x * 32;
    const int mL = tid >> 3;            // 0..31
    const int kqL = (tid & 7) * 4;      // 0..28

    float acc[2][2] = {};
    for (int k0 = 0; k0 < H_; k0 += 32) {
        {
            float4 a = *reinterpret_cast<const float4*>(&g_h[(size_t)mL * H_ + k0 + kqL]);
            As[kqL + 0][mL] = a.x; As[kqL + 1][mL] = a.y;
            As[kqL + 2][mL] = a.z; As[kqL + 3][mL] = a.w;
            float4 w = *reinterpret_cast<const float4*>(&W_hh[(size_t)(n0 + mL) * H_ + k0 + kqL]);
            Bs[kqL + 0][mL] = w.x; Bs[kqL + 1][mL] = w.y;
            Bs[kqL + 2][mL] = w.z; Bs[kqL + 3][mL] = w.w;
        }
        __syncthreads();
#pragma unroll
        for (int k = 0; k < 32; k++) {
            float a0 = As[k][ty * 2], a1 = As[k][ty * 2 + 1];
            float b0 = Bs[k][tx * 2], b1 = Bs[k][tx * 2 + 1];
            acc[0][0] += a0 * b0; acc[0][1] += a0 * b1;
            acc[1][0] += a1 * b0; acc[1][1] += a1 * b1;
        }
        __syncthreads();
    }
#pragma unroll
    for (int i = 0; i < 2; i++) {
        int gm = ty * 2 + i;
#pragma unroll
        for (int j = 0; j < 2; j++) {
            int gn = n0 + tx * 2 + j;
            g_gates[(size_t)gm * G4_ + gn] = acc[i][j] + g_xw[(size_t)(t * B_ + gm) * G4_ + gn];
        }
    }
}

// ---------------------------------------------------------------------------
// Kernel 3 (per step): LSTM cell update + attention. One block per batch b.
__global__ __launch_bounds__(256) void k_lstm_attn(const float* __restrict__ enc) {
    const int b = blockIdx.x;
    const int tid = threadIdx.x;
    __shared__ float h_s[H_];
    __shared__ float sc[S_];

    // LSTM cell: each thread handles 4 consecutive j (float4 loads)
    {
        const float* gates = g_gates + (size_t)b * G4_;
        const int j4 = tid * 4;
        float4 ig = *reinterpret_cast<const float4*>(&gates[j4]);
        float4 fg = *reinterpret_cast<const float4*>(&gates[H_ + j4]);
        float4 gg = *reinterpret_cast<const float4*>(&gates[2 * H_ + j4]);
        float4 og = *reinterpret_cast<const float4*>(&gates[3 * H_ + j4]);
        float4 cv = *reinterpret_cast<const float4*>(&g_c[(size_t)b * H_ + j4]);
        float ia[4] = {ig.x, ig.y, ig.z, ig.w};
        float fa[4] = {fg.x, fg.y, fg.z, fg.w};
        float ga[4] = {gg.x, gg.y, gg.z, gg.w};
        float oa[4] = {og.x, og.y, og.z, og.w};
        float ca[4] = {cv.x, cv.y, cv.z, cv.w};
        float hn[4], cn[4];
#pragma unroll
        for (int q = 0; q < 4; q++) {
            float si = 1.f / (1.f + expf(-ia[q]));
            float sf = 1.f / (1.f + expf(-fa[q]));
            float so = 1.f / (1.f + expf(-oa[q]));
            float cc = sf * ca[q] + si * tanhf(ga[q]);
            cn[q] = cc;
            hn[q] = so * tanhf(cc);
            h_s[j4 + q] = hn[q];
        }
        *reinterpret_cast<float4*>(&g_c[(size_t)b * H_ + j4]) =
            make_float4(cn[0], cn[1], cn[2], cn[3]);
        float4 hv = make_float4(hn[0], hn[1], hn[2], hn[3]);
        *reinterpret_cast<float4*>(&g_h[(size_t)b * H_ + j4]) = hv;
        *reinterpret_cast<float4*>(&g_hc[(size_t)b * 2 * H_ + j4]) = hv;
    }
    __syncthreads();

    const int warp = tid >> 5, lane = tid & 31;
    const float* encb = enc + (size_t)b * S_ * H_;
    // scores: 8 warps x 8 s-values, float4 lane-strided dot of length 1024
#pragma unroll
    for (int i = 0; i < 8; i++) {
        int s = warp * 8 + i;
        float v = 0.f;
        const float* er = encb + (size_t)s * H_;
#pragma unroll
        for (int k4 = 0; k4 < H_ / 128; k4++) {
            int k = (k4 * 32 + lane) * 4;
            float4 e4 = *reinterpret_cast<const float4*>(&er[k]);
            float4 h4 = *reinterpret_cast<const float4*>(&h_s[k]);
            v += e4.x * h4.x + e4.y * h4.y + e4.z * h4.z + e4.w * h4.w;
        }
#pragma unroll
        for (int o = 16; o > 0; o >>= 1) v += __shfl_xor_sync(0xffffffffu, v, o);
        if (lane == 0) sc[s] = v;
    }
    __syncthreads();

    // softmax over 64 scores: warp 0
    if (warp == 0) {
        float v0 = sc[lane], v1 = sc[lane + 32];
        float m = fmaxf(v0, v1);
#pragma unroll
        for (int o = 16; o > 0; o >>= 1) m = fmaxf(m, __shfl_xor_sync(0xffffffffu, m, o));
        float e0 = expf(v0 - m), e1 = expf(v1 - m);
        float ssum = e0 + e1;
#pragma unroll
        for (int o = 16; o > 0; o >>= 1) ssum += __shfl_xor_sync(0xffffffffu, ssum, o);
        float inv = 1.f / ssum;
        sc[lane] = e0 * inv;
        sc[lane + 32] = e1 * inv;
    }
    __syncthreads();

    // context = attn @ enc; each thread owns 4 consecutive hk (float4)
    {
        const int hk4 = tid * 4;
        float cx = 0.f, cy = 0.f, cz = 0.f, cw = 0.f;
#pragma unroll 8
        for (int s = 0; s < S_; s++) {
            float a = sc[s];
            float4 e4 = *reinterpret_cast<const float4*>(&encb[(size_t)s * H_ + hk4]);
            cx += a * e4.x; cy += a * e4.y; cz += a * e4.z; cw += a * e4.w;
        }
        *reinterpret_cast<float4*>(&g_hc[(size_t)b * 2 * H_ + H_ + hk4]) =
            make_float4(cx, cy, cz, cw);
    }
}

// ---------------------------------------------------------------------------
// Kernel 4 (per step): g_dec[t*32+m, n] = tanh( sum_k g_hc[m,k]*W_w[n,k] + b_w[n] )
// M=32, N=1024, K=2048. 32x32 tile, BK=32. grid=32. float4 loads.
__global__ __launch_bounds__(256) void k_gemm_w(
    const float* __restrict__ W_w, const float* __restrict__ b_w, int t)
{
    __shared__ float As[32][33];
    __shared__ float Bs[32][33];
    const int tid = threadIdx.x;
    const int tx = tid & 15, ty = tid >> 4;
    const int n0 = blockIdx.x * 32;
    const int mL = tid >> 3;            // 0..31
    const int kqL = (tid & 7) * 4;      // 0..28

    float acc[2][2] = {};
    for (int k0 = 0; k0 < 2 * H_; k0 += 32) {
        {
            float4 a = *reinterpret_cast<const float4*>(&g_hc[(size_t)mL * 2 * H_ + k0 + kqL]);
            As[kqL + 0][mL] = a.x; As[kqL + 1][mL] = a.y;
            As[kqL + 2][mL] = a.z; As[kqL + 3][mL] = a.w;
            float4 w = *reinterpret_cast<const float4*>(&W_w[(size_t)(n0 + mL) * 2 * H_ + k0 + kqL]);
            Bs[kqL + 0][mL] = w.x; Bs[kqL + 1][mL] = w.y;
            Bs[kqL + 2][mL] = w.z; Bs[kqL + 3][mL] = w.w;
        }
        __syncthreads();
#pragma unroll
        for (int k = 0; k < 32; k++) {
            float a0 = As[k][ty * 2], a1 = As[k][ty * 2 + 1];
            float b0 = Bs[k][tx * 2], b1 = Bs[k][tx * 2 + 1];
            acc[0][0] += a0 * b0; acc[0][1] += a0 * b1;
            acc[1][0] += a1 * b0; acc[1][1] += a1 * b1;
        }
        __syncthreads();
    }
#pragma unroll
    for (int i = 0; i < 2; i++) {
        int gm = ty * 2 + i;
#pragma unroll
        for (int j = 0; j < 2; j++) {
            int gn = n0 + tx * 2 + j;
            g_dec[(size_t)(t * B_ + gm) * H_ + gn] = tanhf(acc[i][j] + b_w[gn]);
        }
    }
}

// ---------------------------------------------------------------------------
// Kernel 5: out[(b*63+t), v] = sum_k g_dec[t*32+b, k]*W_out[v,k] + b_out[v]
// M=2048(pad), N=32000, K=1024.
// 128x128 tile, BK=16, 256 threads, 8x8 micro-tile, float4 global loads.
// grid = (N/128=250, M/128=16).
__global__ __launch_bounds__(256) void k_gemm_out(
    const float* __restrict__ W_out, const float* __restrict__ b_out,
    float* __restrict__ out)
{
    __shared__ float As[16][132];   // [k][m], m in 0..127
    __shared__ float Bs[16][132];   // [k][n], n in 0..127
    const int tid = threadIdx.x;
    const int tx = tid & 15;        // 0..15 -> n micro (8 cols each)
    const int ty = tid >> 4;        // 0..15 -> m micro (8 rows each)
    const int n0 = blockIdx.x * 128;
    const int m0 = blockIdx.y * 128;

    float acc[8][8] = {};

    for (int k0 = 0; k0 < H_; k0 += 16) {
        // A: 128 rows x 16 k = 512 float4, 2 per thread; B: same.
#pragma unroll
        for (int e = 0; e < 2; e++) {
            int f = tid + e * 256;
            int m = f >> 2;               // 0..127
            int kq = (f & 3) * 4;         // 0,4,8,12
            float4 v = *reinterpret_cast<const float4*>(
                &g_dec[(size_t)(m0 + m) * H_ + k0 + kq]);
            As[kq + 0][m] = v.x;
            As[kq + 1][m] = v.y;
            As[kq + 2][m] = v.z;
            As[kq + 3][m] = v.w;
            float4 w = *reinterpret_cast<const float4*>(
                &W_out[(size_t)(n0 + m) * H_ + k0 + kq]);
            Bs[kq + 0][m] = w.x;
            Bs[kq + 1][m] = w.y;
            Bs[kq + 2][m] = w.z;
            Bs[kq + 3][m] = w.w;
        }
        __syncthreads();

#pragma unroll
        for (int k = 0; k < 16; k++) {
            float a[8], bb[8];
#pragma unroll
            for (int i = 0; i < 8; i++) a[i]  = As[k][ty * 8 + i];
#pragma unroll
            for (int j = 0; j < 8; j++) bb[j] = Bs[k][tx * 8 + j];
#pragma unroll
            for (int i = 0; i < 8; i++)
#pragma unroll
                for (int j = 0; j < 8; j++) acc[i][j] += a[i] * bb[j];
        }
        __syncthreads();
    }

#pragma unroll
    for (int i = 0; i < 8; i++) {
        int gm = m0 + ty * 8 + i;
        if (gm < M2_) {
            int t = gm >> 5, b = gm & 31;
            float* orow = out + ((size_t)(b * TS_ + t)) * V_;
#pragma unroll
            for (int j = 0; j < 8; j++) {
                int gn = n0 + tx * 8 + j;
                orow[gn] = acc[i][j] + b_out[gn];
            }
        }
    }
}

// ---------------------------------------------------------------------------
extern "C" void kernel_launch(void* const* d_in, const int* in_sizes, int n_in,
                              void* d_out, int out_size) {
    const int*   tgt   = (const int*)  d_in[0];
    const float* h0    = (const float*)d_in[1];
    const float* c0    = (const float*)d_in[2];
    const float* enc   = (const float*)d_in[3];
    const float* emb   = (const float*)d_in[4];
    const float* W_ih  = (const float*)d_in[5];
    const float* W_hh  = (const float*)d_in[6];
    const float* b_ih  = (const float*)d_in[7];
    const float* b_hh  = (const float*)d_in[8];
    const float* W_w   = (const float*)d_in[9];
    const float* b_w   = (const float*)d_in[10];
    const float* W_out = (const float*)d_in[11];
    const float* b_out = (const float*)d_in[12];
    float* out = (float*)d_out;

    k_init<<<(B_ * H_ + 255) / 256, 256>>>(h0, c0);
    k_embed_xw<<<dim3(G4_ / 64, MP_ / 64), 256>>>(tgt, emb, W_ih, b_ih, b_hh);
    for (int t = 0; t < TS_; t++) {
        k_gemm_hh<<<G4_ / 32, 256>>>(W_hh, t);
        k_lstm_attn<<<B_, 256>>>(enc);
        k_gemm_w<<<H_ / 32, 256>>>(W_w, b_w, t);
    }
    k_gemm_out<<<dim3(V_ / 128, MP_ / 128), 256>>>(W_out, b_out, out);
}